// round 4
// baseline (speedup 1.0000x reference)
#include <cuda_runtime.h>
#include <cuda_bf16.h>
#include <cstdint>

// ---------------------------------------------------------------------------
// Problem constants
// ---------------------------------------------------------------------------
static constexpr int TOK = 2048;
static constexpr int D   = 1024;
static constexpr int H3  = 3072;
static constexpr int NH  = 16;
static constexpr int NOFF = 44;

__device__ __constant__ int c_offs[NOFF] = {
    0,1,2,3,4,5,6,7,8,9,10,11,12,13,14,15,16,17,18,19,20,21,22,23,24,
    25,26,27,28,29,30,31,32,48,64,96,128,192,256,384,512,768,1024,1536};

// ---------------------------------------------------------------------------
// Scratch (allocation-free)
// ---------------------------------------------------------------------------
__device__ float g_qkv [TOK * H3];
__device__ float g_gate[TOK * D];
__device__ __nv_bfloat16 g_xh [TOK * D],        g_xl [TOK * D];
__device__ __nv_bfloat16 g_wfh[(H3 + D) * D],   g_wfl[(H3 + D) * D];  // [Wqkv; Wgate]
__device__ __nv_bfloat16 g_woh[D * D],          g_wol[D * D];
__device__ __nv_bfloat16 g_a2h[TOK * D],        g_a2l[TOK * D];

// ---------------------------------------------------------------------------
// PTX helpers (portable sm_80+ PTX only — no 'a'-target features)
// ---------------------------------------------------------------------------
__device__ __forceinline__ uint32_t smem_u32(const void* p) {
    uint32_t a;
    asm("{ .reg .u64 t; cvta.to.shared.u64 t, %1; cvt.u32.u64 %0, t; }"
        : "=r"(a) : "l"(p));
    return a;
}

#define CP_ASYNC16(dst, src) \
    asm volatile("cp.async.cg.shared.global [%0], [%1], 16;" :: "r"(dst), "l"(src))
#define CP_COMMIT() asm volatile("cp.async.commit_group;" ::: "memory")
#define CP_WAIT1()  asm volatile("cp.async.wait_group 1;"  ::: "memory")

#define LDMX4(r, addr) \
    asm volatile("ldmatrix.sync.aligned.m8n8.x4.shared.b16 {%0,%1,%2,%3}, [%4];" \
                 : "=r"((r)[0]), "=r"((r)[1]), "=r"((r)[2]), "=r"((r)[3]) : "r"(addr))

#define MMA16816(d, a, b0, b1) \
    asm volatile("mma.sync.aligned.m16n8k16.row.col.f32.bf16.bf16.f32 " \
                 "{%0,%1,%2,%3}, {%4,%5,%6,%7}, {%8,%9}, {%0,%1,%2,%3};" \
                 : "+f"((d)[0]), "+f"((d)[1]), "+f"((d)[2]), "+f"((d)[3]) \
                 : "r"((a)[0]), "r"((a)[1]), "r"((a)[2]), "r"((a)[3]), \
                   "r"(b0), "r"(b1))

// ---------------------------------------------------------------------------
// Fused fp32 -> bf16 hi/lo split for x, Wqkv, Wgate, Wout in ONE launch
// ---------------------------------------------------------------------------
static constexpr int X4  = TOK * D / 4;        // 524288
static constexpr int WQ4 = H3 * D / 4;         // 786432
static constexpr int WG4 = D * D / 4;          // 262144
static constexpr int WO4 = D * D / 4;          // 262144
static constexpr int TOT4 = X4 + WQ4 + WG4 + WO4;

__global__ __launch_bounds__(256) void split_all_kernel(
    const float4* __restrict__ x, const float4* __restrict__ wq,
    const float4* __restrict__ wg, const float4* __restrict__ wo,
    uint2* __restrict__ xh, uint2* __restrict__ xl,
    uint2* __restrict__ wfh, uint2* __restrict__ wfl,
    uint2* __restrict__ woh, uint2* __restrict__ wol)
{
    int i = blockIdx.x * 256 + threadIdx.x;
    if (i >= TOT4) return;

    const float4* src; uint2 *dh, *dl; int j;
    if (i < X4)                 { src = x;  dh = xh;  dl = xl;  j = i; }
    else if (i < X4 + WQ4)      { src = wq; dh = wfh; dl = wfl; j = i - X4; }
    else if (i < X4 + WQ4 + WG4){ src = wg; dh = wfh + WQ4; dl = wfl + WQ4; j = i - X4 - WQ4; }
    else                        { src = wo; dh = woh; dl = wol; j = i - X4 - WQ4 - WG4; }

    float4 a = src[j];
    float av[4] = {a.x, a.y, a.z, a.w};
    uint32_t hh[4], ll[4];
#pragma unroll
    for (int k = 0; k < 4; k++) {
        __nv_bfloat16 h = __float2bfloat16(av[k]);
        float r = av[k] - __bfloat162float(h);
        __nv_bfloat16 l = __float2bfloat16(r);
        hh[k] = (uint32_t)__bfloat16_as_ushort(h);
        ll[k] = (uint32_t)__bfloat16_as_ushort(l);
    }
    uint2 hv, lv;
    hv.x = hh[0] | (hh[1] << 16); hv.y = hh[2] | (hh[3] << 16);
    lv.x = ll[0] | (ll[1] << 16); lv.y = ll[2] | (ll[3] << 16);
    dh[j] = hv; dl[j] = lv;
}

// ---------------------------------------------------------------------------
// HMMA GEMM, 3-term bf16 split, CTA tile 128x128, 4 warps (64x64 warp tile),
// 3-stage cp.async pipeline. Dual epilogue:
//   n <  NSPLIT : C0[m, n]          = acc + bias0[n]
//   n >= NSPLIT : C1[m, n-NSPLIT]   = sigmoid(acc + bias1[n-NSPLIT])
// (NSPLIT is a multiple of 128 -> per-CTA uniform branch)
// ---------------------------------------------------------------------------
__global__ __launch_bounds__(128, 2) void hmma_gemm(
    const __nv_bfloat16* __restrict__ Ah, const __nv_bfloat16* __restrict__ Al,
    const __nv_bfloat16* __restrict__ Bh, const __nv_bfloat16* __restrict__ Bl,
    const float* __restrict__ bias0, const float* __restrict__ bias1,
    float* __restrict__ C0, float* __restrict__ C1,
    int N, int K, int NSPLIT)
{
    extern __shared__ char smraw[];
    const uint32_t sb = (smem_u32(smraw) + 127u) & ~127u;
    // stage s (s=0..2): A at sb + s*32768, B at +16384 (128 rows x 128B, SW128)

    const int tid  = threadIdx.x;
    const int lane = tid & 31;
    const int wid  = tid >> 5;
    const int wm   = wid & 1;    // 0..1 -> 64-row slab
    const int wn   = wid >> 1;   // 0..1 -> 64-col slab
    const int m0 = blockIdx.y * 128;
    const int n0 = blockIdx.x * 128;

    const __nv_bfloat16* Aseg[3] = {Ah, Al, Ah};
    const __nv_bfloat16* Bseg[3] = {Bh, Bh, Bl};
    const int kc64   = K >> 6;
    const int nchunk = 3 * kc64;

    float acc[4][8][4];
#pragma unroll
    for (int a = 0; a < 4; a++)
#pragma unroll
        for (int b = 0; b < 8; b++)
#pragma unroll
            for (int c = 0; c < 4; c++) acc[a][b][c] = 0.f;

    // ldmatrix per-thread geometry (same mapping verified in R3)
    const int a_r  = wm * 64 + ((lane >> 3) & 1) * 8 + (lane & 7);
    const int a_kc = (lane >> 4);
    const int b_r  = wn * 64 + ((lane >> 4) & 1) * 8 + (lane & 7);
    const int b_kc = ((lane >> 3) & 1);

    // loader: 1024 16B chunks per tile, 128 threads -> 8 chunks/thread/tile
    auto load_tile = [&](int i) {
        const int seg = i / kc64;
        const int kb  = (i - seg * kc64) * 64;
        const uint32_t abase = sb + (uint32_t)(i % 3) * 32768u;
        const uint32_t bbase = abase + 16384u;
        const __nv_bfloat16* Ag = Aseg[seg];
        const __nv_bfloat16* Bg = Bseg[seg];
#pragma unroll
        for (int t = 0; t < 8; t++) {
            int u = tid + t * 128;
            int row = u >> 3, c = u & 7;
            uint32_t dst = abase + (uint32_t)row * 128u + (uint32_t)((c ^ (row & 7)) * 16);
            CP_ASYNC16(dst, (const void*)(Ag + (size_t)(m0 + row) * K + kb + c * 8));
        }
#pragma unroll
        for (int t = 0; t < 8; t++) {
            int u = tid + t * 128;
            int row = u >> 3, c = u & 7;
            uint32_t dst = bbase + (uint32_t)row * 128u + (uint32_t)((c ^ (row & 7)) * 16);
            CP_ASYNC16(dst, (const void*)(Bg + (size_t)(n0 + row) * K + kb + c * 8));
        }
    };

    load_tile(0); CP_COMMIT();
    load_tile(1); CP_COMMIT();

    for (int i = 0; i < nchunk; i++) {
        CP_WAIT1();
        __syncthreads();

        const uint32_t abase = sb + (uint32_t)(i % 3) * 32768u;
        const uint32_t bbase = abase + 16384u;

#pragma unroll
        for (int ks = 0; ks < 4; ks++) {
            uint32_t afr[4][4], bfr[4][4];
#pragma unroll
            for (int mi = 0; mi < 4; mi++) {
                int r = a_r + mi * 16;
                uint32_t addr = abase + (uint32_t)r * 128u
                              + (uint32_t)(((ks * 2 + a_kc) ^ (r & 7)) * 16);
                LDMX4(afr[mi], addr);
            }
#pragma unroll
            for (int ng = 0; ng < 4; ng++) {
                int r = b_r + ng * 16;
                uint32_t addr = bbase + (uint32_t)r * 128u
                              + (uint32_t)(((ks * 2 + b_kc) ^ (r & 7)) * 16);
                LDMX4(bfr[ng], addr);
            }
#pragma unroll
            for (int mi = 0; mi < 4; mi++)
#pragma unroll
                for (int ni = 0; ni < 8; ni++)
                    MMA16816(acc[mi][ni], afr[mi],
                             bfr[ni >> 1][(ni & 1) * 2], bfr[ni >> 1][(ni & 1) * 2 + 1]);
        }

        if (i + 2 < nchunk) load_tile(i + 2);
        CP_COMMIT();
    }

    // ---- epilogue (per-CTA uniform output selection) ----
    const bool  gate_tile = (n0 >= NSPLIT);
    float*       Cb   = gate_tile ? C1 : C0;
    const float* bb   = gate_tile ? bias1 : bias0;
    const int    ncols = gate_tile ? (N - NSPLIT) : NSPLIT;
    const int    nb0   = n0 - (gate_tile ? NSPLIT : 0);

    const int mrow = lane >> 2;
    const int ncol = (lane & 3) * 2;
#pragma unroll
    for (int mi = 0; mi < 4; mi++) {
#pragma unroll
        for (int half = 0; half < 2; half++) {
            const int m = m0 + wm * 64 + mi * 16 + mrow + half * 8;
            float* crow = Cb + (size_t)m * ncols;
#pragma unroll
            for (int ni = 0; ni < 8; ni++) {
                const int n = nb0 + wn * 64 + ni * 8 + ncol;
                float v0 = acc[mi][ni][half * 2 + 0] + bb[n];
                float v1 = acc[mi][ni][half * 2 + 1] + bb[n + 1];
                if (gate_tile) {
                    v0 = 1.f / (1.f + __expf(-v0));
                    v1 = 1.f / (1.f + __expf(-v1));
                }
                float2 o = {v0, v1};
                *(float2*)(crow + n) = o;
            }
        }
    }
}

// ---------------------------------------------------------------------------
// Attention: one warp per (token, head), lane owns dims {2l, 2l+1} (float2),
// fused gate multiply, emits bf16-split a2.
// ---------------------------------------------------------------------------
__global__ __launch_bounds__(256) void attn_kernel(
    const float* __restrict__ qkv, const float* __restrict__ gate,
    const float* __restrict__ pos_bias,
    __nv_bfloat16* __restrict__ a2h, __nv_bfloat16* __restrict__ a2l)
{
    const int gwarp = (blockIdx.x * blockDim.x + threadIdx.x) >> 5;
    const int lane  = threadIdx.x & 31;
    const int n = gwarp >> 4;
    const int h = gwarp & 15;
    if (n >= TOK) return;

    const float2 q2 = *(const float2*)(qkv + (size_t)n * H3 + h * 64 + lane * 2);

    const float NEG = -1e30f;
    float s0 = NEG, s1 = NEG;

#pragma unroll
    for (int o = 0; o < NOFF; o++) {
        const int off = c_offs[o];
        const int src = n - off;
        float sc = NEG;
        if (src >= 0) {
            const float2 k2 = *(const float2*)(qkv + (size_t)src * H3 + D + h * 64 + lane * 2);
            float p = q2.x * k2.x + q2.y * k2.y;
            p += __shfl_xor_sync(0xffffffffu, p, 16);
            p += __shfl_xor_sync(0xffffffffu, p, 8);
            p += __shfl_xor_sync(0xffffffffu, p, 4);
            p += __shfl_xor_sync(0xffffffffu, p, 2);
            p += __shfl_xor_sync(0xffffffffu, p, 1);
            sc = p * 0.125f + pos_bias[o * NH + h];
        }
        if ((o & 31) == lane) {
            if (o < 32) s0 = sc; else s1 = sc;
        }
    }

    float m = fmaxf(s0, s1);
    m = fmaxf(m, __shfl_xor_sync(0xffffffffu, m, 16));
    m = fmaxf(m, __shfl_xor_sync(0xffffffffu, m, 8));
    m = fmaxf(m, __shfl_xor_sync(0xffffffffu, m, 4));
    m = fmaxf(m, __shfl_xor_sync(0xffffffffu, m, 2));
    m = fmaxf(m, __shfl_xor_sync(0xffffffffu, m, 1));

    float e0 = (s0 > NEG) ? __expf(s0 - m) : 0.f;
    float e1 = (s1 > NEG) ? __expf(s1 - m) : 0.f;

    float sum = e0 + e1;
    sum += __shfl_xor_sync(0xffffffffu, sum, 16);
    sum += __shfl_xor_sync(0xffffffffu, sum, 8);
    sum += __shfl_xor_sync(0xffffffffu, sum, 4);
    sum += __shfl_xor_sync(0xffffffffu, sum, 2);
    sum += __shfl_xor_sync(0xffffffffu, sum, 1);
    const float inv = 1.f / sum;

    float acc0 = 0.f, acc1 = 0.f;
#pragma unroll
    for (int o = 0; o < NOFF; o++) {
        const int off = c_offs[o];
        const int src = n - off;
        if (src >= 0) {
            float ev = (o < 32) ? e0 : e1;
            float al = __shfl_sync(0xffffffffu, ev, o & 31);
            const float2 v2 = *(const float2*)(qkv + (size_t)src * H3 + 2 * D + h * 64 + lane * 2);
            acc0 = fmaf(al, v2.x, acc0);
            acc1 = fmaf(al, v2.y, acc1);
        }
    }
    acc0 *= inv;
    acc1 *= inv;

    const int oi = n * D + h * 64 + lane * 2;
    const float2 g2 = *(const float2*)(gate + oi);
    float v0 = acc0 * g2.x;
    float v1 = acc1 * g2.y;

    __nv_bfloat16 h0 = __float2bfloat16(v0);
    __nv_bfloat16 h1 = __float2bfloat16(v1);
    a2h[oi]     = h0;
    a2h[oi + 1] = h1;
    a2l[oi]     = __float2bfloat16(v0 - __bfloat162float(h0));
    a2l[oi + 1] = __float2bfloat16(v1 - __bfloat162float(h1));
}

// ---------------------------------------------------------------------------
// kernel_launch
// ---------------------------------------------------------------------------
extern "C" void kernel_launch(void* const* d_in, const int* in_sizes, int n_in,
                              void* d_out, int out_size)
{
    const float* x        = (const float*)d_in[0];
    const float* Wqkv     = (const float*)d_in[1];
    const float* bqkv     = (const float*)d_in[2];
    const float* Wout     = (const float*)d_in[3];
    const float* bout     = (const float*)d_in[4];
    const float* Wgate    = (const float*)d_in[5];
    const float* bgate    = (const float*)d_in[6];
    const float* pos_bias = (const float*)d_in[7];
    float* out = (float*)d_out;

    float *qkv, *gate;
    __nv_bfloat16 *xh, *xl, *wfh, *wfl, *woh, *wol, *a2h, *a2l;
    cudaGetSymbolAddress((void**)&qkv,  g_qkv);
    cudaGetSymbolAddress((void**)&gate, g_gate);
    cudaGetSymbolAddress((void**)&xh,  g_xh);  cudaGetSymbolAddress((void**)&xl,  g_xl);
    cudaGetSymbolAddress((void**)&wfh, g_wfh); cudaGetSymbolAddress((void**)&wfl, g_wfl);
    cudaGetSymbolAddress((void**)&woh, g_woh); cudaGetSymbolAddress((void**)&wol, g_wol);
    cudaGetSymbolAddress((void**)&a2h, g_a2h); cudaGetSymbolAddress((void**)&a2l, g_a2l);

    const int SMEM_BYTES = 128 + 3 * 32768;   // pad + 3 stages x (A 16K + B 16K)
    cudaFuncSetAttribute(hmma_gemm, cudaFuncAttributeMaxDynamicSharedMemorySize, SMEM_BYTES);

    // 1) all fp32 -> bf16 hi/lo splits (one launch)
    split_all_kernel<<<(TOT4 + 255) / 256, 256>>>(
        (const float4*)x, (const float4*)Wqkv, (const float4*)Wgate, (const float4*)Wout,
        (uint2*)xh, (uint2*)xl, (uint2*)wfh, (uint2*)wfl, (uint2*)woh, (uint2*)wol);

    // 2) fused qkv+gate GEMM: [2048, 4096] = x @ [Wqkv; Wgate]^T
    //    cols 0..3071 -> qkv (+bqkv), cols 3072..4095 -> sigmoid -> gate (+bgate)
    hmma_gemm<<<dim3((H3 + D) / 128, TOK / 128), 128, SMEM_BYTES>>>(
        xh, xl, wfh, wfl, bqkv, bgate, qkv, gate, H3 + D, D, H3);

    // 3) attention + gate -> split a2
    attn_kernel<<<(TOK * NH) / 8, 256>>>(qkv, gate, pos_bias, a2h, a2l);

    // 4) out = a2 @ Wout^T + bout
    hmma_gemm<<<dim3(D / 128, TOK / 128), 128, SMEM_BYTES>>>(
        a2h, a2l, woh, wol, bout, bout, out, nullptr, D, D, D);
}

// round 5
// speedup vs baseline: 2.4162x; 2.4162x over previous
#include <cuda_runtime.h>
#include <cuda_bf16.h>
#include <cstdint>

// ---------------------------------------------------------------------------
// Problem constants
// ---------------------------------------------------------------------------
static constexpr int TOK = 2048;
static constexpr int D   = 1024;
static constexpr int H3  = 3072;
static constexpr int NH  = 16;
static constexpr int NOFF = 44;

__device__ __constant__ int c_offs[NOFF] = {
    0,1,2,3,4,5,6,7,8,9,10,11,12,13,14,15,16,17,18,19,20,21,22,23,24,
    25,26,27,28,29,30,31,32,48,64,96,128,192,256,384,512,768,1024,1536};

// ---------------------------------------------------------------------------
// Scratch (allocation-free)
// ---------------------------------------------------------------------------
__device__ float g_qkv [TOK * H3];
__device__ float g_gate[TOK * D];
__device__ __nv_bfloat16 g_xh [TOK * D],      g_xl [TOK * D];
__device__ __nv_bfloat16 g_wfh[(H3 + D) * D], g_wfl[(H3 + D) * D];  // [Wqkv; Wgate]
__device__ __nv_bfloat16 g_woh[D * D],        g_wol[D * D];
__device__ __nv_bfloat16 g_a2h[TOK * D],      g_a2l[TOK * D];

// ---------------------------------------------------------------------------
// PTX helpers (portable sm_80+ PTX only)
// ---------------------------------------------------------------------------
__device__ __forceinline__ uint32_t smem_u32(const void* p) {
    uint32_t a;
    asm("{ .reg .u64 t; cvta.to.shared.u64 t, %1; cvt.u32.u64 %0, t; }"
        : "=r"(a) : "l"(p));
    return a;
}

#define CP_ASYNC16(dst, src) \
    asm volatile("cp.async.cg.shared.global [%0], [%1], 16;" :: "r"(dst), "l"(src))
#define CP_COMMIT() asm volatile("cp.async.commit_group;" ::: "memory")
#define CP_WAIT1()  asm volatile("cp.async.wait_group 1;"  ::: "memory")

#define LDMX4(r, addr) \
    asm volatile("ldmatrix.sync.aligned.m8n8.x4.shared.b16 {%0,%1,%2,%3}, [%4];" \
                 : "=r"((r)[0]), "=r"((r)[1]), "=r"((r)[2]), "=r"((r)[3]) : "r"(addr))

#define MMA16816(d, a, b0, b1) \
    asm volatile("mma.sync.aligned.m16n8k16.row.col.f32.bf16.bf16.f32 " \
                 "{%0,%1,%2,%3}, {%4,%5,%6,%7}, {%8,%9}, {%0,%1,%2,%3};" \
                 : "+f"((d)[0]), "+f"((d)[1]), "+f"((d)[2]), "+f"((d)[3]) \
                 : "r"((a)[0]), "r"((a)[1]), "r"((a)[2]), "r"((a)[3]), \
                   "r"(b0), "r"(b1))

// ---------------------------------------------------------------------------
// Fused fp32 -> bf16 hi/lo split for x, Wqkv, Wgate, Wout in ONE launch
// ---------------------------------------------------------------------------
static constexpr int X4  = TOK * D / 4;
static constexpr int WQ4 = H3 * D / 4;
static constexpr int WG4 = D * D / 4;
static constexpr int WO4 = D * D / 4;
static constexpr int TOT4 = X4 + WQ4 + WG4 + WO4;

__global__ __launch_bounds__(256) void split_all_kernel(
    const float4* __restrict__ x, const float4* __restrict__ wq,
    const float4* __restrict__ wg, const float4* __restrict__ wo,
    uint2* __restrict__ xh, uint2* __restrict__ xl,
    uint2* __restrict__ wfh, uint2* __restrict__ wfl,
    uint2* __restrict__ woh, uint2* __restrict__ wol)
{
    int i = blockIdx.x * 256 + threadIdx.x;
    if (i >= TOT4) return;

    const float4* src; uint2 *dh, *dl; int j;
    if (i < X4)                 { src = x;  dh = xh;  dl = xl;  j = i; }
    else if (i < X4 + WQ4)      { src = wq; dh = wfh; dl = wfl; j = i - X4; }
    else if (i < X4 + WQ4 + WG4){ src = wg; dh = wfh + WQ4; dl = wfl + WQ4; j = i - X4 - WQ4; }
    else                        { src = wo; dh = woh; dl = wol; j = i - X4 - WQ4 - WG4; }

    float4 a = src[j];
    float av[4] = {a.x, a.y, a.z, a.w};
    uint32_t hh[4], ll[4];
#pragma unroll
    for (int k = 0; k < 4; k++) {
        __nv_bfloat16 h = __float2bfloat16(av[k]);
        float r = av[k] - __bfloat162float(h);
        __nv_bfloat16 l = __float2bfloat16(r);
        hh[k] = (uint32_t)__bfloat16_as_ushort(h);
        ll[k] = (uint32_t)__bfloat16_as_ushort(l);
    }
    uint2 hv, lv;
    hv.x = hh[0] | (hh[1] << 16); hv.y = hh[2] | (hh[3] << 16);
    lv.x = ll[0] | (ll[1] << 16); lv.y = ll[2] | (ll[3] << 16);
    dh[j] = hv; dl[j] = lv;
}

// ---------------------------------------------------------------------------
// HMMA GEMM (R3-proven config): CTA 128x128, 8 warps (64x32 warp tile),
// 2-stage cp.async double buffer, 3-term bf16 split.
// Dual epilogue (per-CTA uniform): n < NSPLIT -> C0+bias0 ; else sigmoid->C1.
// ---------------------------------------------------------------------------
__global__ __launch_bounds__(256) void hmma_gemm(
    const __nv_bfloat16* __restrict__ Ah, const __nv_bfloat16* __restrict__ Al,
    const __nv_bfloat16* __restrict__ Bh, const __nv_bfloat16* __restrict__ Bl,
    const float* __restrict__ bias0, const float* __restrict__ bias1,
    float* __restrict__ C0, float* __restrict__ C1,
    int N, int K, int NSPLIT)
{
    extern __shared__ char smraw[];
    uint32_t sb = (smem_u32(smraw) + 127u) & ~127u;

    const int tid  = threadIdx.x;
    const int lane = tid & 31;
    const int wid  = tid >> 5;
    const int wm   = wid & 1;       // 0..1 -> 64-row slab
    const int wn   = wid >> 1;      // 0..3 -> 32-col slab
    const int m0 = blockIdx.y * 128;
    const int n0 = blockIdx.x * 128;

    const __nv_bfloat16* Aseg[3] = {Ah, Al, Ah};
    const __nv_bfloat16* Bseg[3] = {Bh, Bh, Bl};
    const int kc64   = K >> 6;
    const int nchunk = 3 * kc64;

    float acc[4][4][4];
#pragma unroll
    for (int i = 0; i < 4; i++)
#pragma unroll
        for (int j = 0; j < 4; j++)
#pragma unroll
            for (int q = 0; q < 4; q++) acc[i][j][q] = 0.f;

    const int a_r  = wm * 64 + ((lane >> 3) & 1) * 8 + (lane & 7);
    const int a_kc = (lane >> 4);
    const int b_r  = wn * 32 + ((lane >> 4) & 1) * 8 + (lane & 7);
    const int b_kc = ((lane >> 3) & 1);

    auto load_tile = [&](int i) {
        const int seg = i / kc64;
        const int kb  = (i - seg * kc64) * 64;
        const int st  = i & 1;
        const uint32_t abase = sb + st * 32768u;
        const uint32_t bbase = abase + 16384u;
        const __nv_bfloat16* Ag = Aseg[seg];
        const __nv_bfloat16* Bg = Bseg[seg];
#pragma unroll
        for (int t = 0; t < 4; t++) {
            int u = tid + t * 256;
            int row = u >> 3, c = u & 7;
            uint32_t dst = abase + (uint32_t)row * 128u + (uint32_t)((c ^ (row & 7)) * 16);
            CP_ASYNC16(dst, (const void*)(Ag + (size_t)(m0 + row) * K + kb + c * 8));
        }
#pragma unroll
        for (int t = 0; t < 4; t++) {
            int u = tid + t * 256;
            int row = u >> 3, c = u & 7;
            uint32_t dst = bbase + (uint32_t)row * 128u + (uint32_t)((c ^ (row & 7)) * 16);
            CP_ASYNC16(dst, (const void*)(Bg + (size_t)(n0 + row) * K + kb + c * 8));
        }
    };

    load_tile(0);
    CP_COMMIT();

    for (int i = 0; i < nchunk; i++) {
        if (i + 1 < nchunk) load_tile(i + 1);
        CP_COMMIT();
        CP_WAIT1();
        __syncthreads();

        const int st = i & 1;
        const uint32_t abase = sb + st * 32768u;
        const uint32_t bbase = abase + 16384u;

#pragma unroll
        for (int ks = 0; ks < 4; ks++) {
            uint32_t afr[4][4], bfr[2][4];
#pragma unroll
            for (int mi = 0; mi < 4; mi++) {
                int r = a_r + mi * 16;
                uint32_t addr = abase + (uint32_t)r * 128u
                              + (uint32_t)(((ks * 2 + a_kc) ^ (r & 7)) * 16);
                LDMX4(afr[mi], addr);
            }
#pragma unroll
            for (int ng = 0; ng < 2; ng++) {
                int r = b_r + ng * 16;
                uint32_t addr = bbase + (uint32_t)r * 128u
                              + (uint32_t)(((ks * 2 + b_kc) ^ (r & 7)) * 16);
                LDMX4(bfr[ng], addr);
            }
#pragma unroll
            for (int mi = 0; mi < 4; mi++)
#pragma unroll
                for (int ni = 0; ni < 4; ni++)
                    MMA16816(acc[mi][ni], afr[mi],
                             bfr[ni >> 1][(ni & 1) * 2], bfr[ni >> 1][(ni & 1) * 2 + 1]);
        }
        __syncthreads();
    }

    // dual epilogue (per-CTA uniform branch)
    const bool   gate_tile = (n0 >= NSPLIT);
    float*       Cb    = gate_tile ? C1 : C0;
    const float* bb    = gate_tile ? bias1 : bias0;
    const int    ncols = gate_tile ? (N - NSPLIT) : NSPLIT;
    const int    nb0   = n0 - (gate_tile ? NSPLIT : 0);

    const int mrow = lane >> 2;
    const int ncol = (lane & 3) * 2;
#pragma unroll
    for (int mi = 0; mi < 4; mi++) {
#pragma unroll
        for (int half = 0; half < 2; half++) {
            const int m = m0 + wm * 64 + mi * 16 + mrow + half * 8;
            float* crow = Cb + (size_t)m * ncols;
#pragma unroll
            for (int ni = 0; ni < 4; ni++) {
                const int n = nb0 + wn * 32 + ni * 8 + ncol;
                float v0 = acc[mi][ni][half * 2 + 0] + bb[n];
                float v1 = acc[mi][ni][half * 2 + 1] + bb[n + 1];
                if (gate_tile) {
                    v0 = 1.f / (1.f + __expf(-v0));
                    v1 = 1.f / (1.f + __expf(-v1));
                }
                float2 o = {v0, v1};
                *(float2*)(crow + n) = o;
            }
        }
    }
}

// ---------------------------------------------------------------------------
// Attention: one warp per (token, head), lane owns dims {2l, 2l+1}.
// Dense offsets 0..31 use a butterfly multi-reduce (31 shuffles for all 32
// dot products); sparse offsets (idx 32..43) use the 5-shuffle path.
// Fused gate multiply; emits bf16-split a2.
// ---------------------------------------------------------------------------
__global__ __launch_bounds__(256) void attn_kernel(
    const float* __restrict__ qkv, const float* __restrict__ gate,
    const float* __restrict__ pos_bias,
    __nv_bfloat16* __restrict__ a2h, __nv_bfloat16* __restrict__ a2l)
{
    const int gwarp = (blockIdx.x * blockDim.x + threadIdx.x) >> 5;
    const int lane  = threadIdx.x & 31;
    const int n = gwarp >> 4;
    const int h = gwarp & 15;
    if (n >= TOK) return;

    const float2 q2 = *(const float2*)(qkv + (size_t)n * H3 + h * 64 + lane * 2);
    const float NEG = -1e30f;

    // ---- dense offsets 0..31 (offset == index) ----
    float r[32];
#pragma unroll
    for (int o = 0; o < 32; o++) {
        const int src = n - o;
        float p = 0.f;
        if (src >= 0) {
            const float2 k2 = *(const float2*)(qkv + (size_t)src * H3 + D + h * 64 + lane * 2);
            p = q2.x * k2.x + q2.y * k2.y;
        }
        r[o] = p;
    }
    // butterfly multi-reduce: after 5 stages, lane l holds sum_lanes r[l]
#pragma unroll
    for (int m = 16, cnt = 32; m >= 1; m >>= 1, cnt >>= 1) {
        const int half = cnt >> 1;
        const bool hi = (lane & m) != 0;
#pragma unroll
        for (int i = 0; i < 16; i++) {      // bound by max half; guard below
            if (i < half) {
                float a = r[i], b = r[i + half];
                float sel = hi ? a : b;
                float got = __shfl_xor_sync(0xffffffffu, sel, m);
                r[i] = hi ? (b + got) : (a + got);
            }
        }
    }
    float s0 = (n - lane >= 0) ? (r[0] * 0.125f + pos_bias[lane * NH + h]) : NEG;

    // ---- sparse offsets (indices 32..43) ----
    float s1 = NEG;
#pragma unroll
    for (int oi = 32; oi < NOFF; oi++) {
        const int off = c_offs[oi];
        const int src = n - off;
        float sc = NEG;
        if (src >= 0) {
            const float2 k2 = *(const float2*)(qkv + (size_t)src * H3 + D + h * 64 + lane * 2);
            float p = q2.x * k2.x + q2.y * k2.y;
            p += __shfl_xor_sync(0xffffffffu, p, 16);
            p += __shfl_xor_sync(0xffffffffu, p, 8);
            p += __shfl_xor_sync(0xffffffffu, p, 4);
            p += __shfl_xor_sync(0xffffffffu, p, 2);
            p += __shfl_xor_sync(0xffffffffu, p, 1);
            sc = p * 0.125f + pos_bias[oi * NH + h];
        }
        if (lane == oi - 32) s1 = sc;
    }

    // ---- softmax over 44 scores (s0: lanes=offsets 0..31, s1: lanes 0..11) ----
    float m = fmaxf(s0, s1);
    m = fmaxf(m, __shfl_xor_sync(0xffffffffu, m, 16));
    m = fmaxf(m, __shfl_xor_sync(0xffffffffu, m, 8));
    m = fmaxf(m, __shfl_xor_sync(0xffffffffu, m, 4));
    m = fmaxf(m, __shfl_xor_sync(0xffffffffu, m, 2));
    m = fmaxf(m, __shfl_xor_sync(0xffffffffu, m, 1));

    float e0 = (s0 > NEG) ? __expf(s0 - m) : 0.f;
    float e1 = (s1 > NEG) ? __expf(s1 - m) : 0.f;

    float sum = e0 + e1;
    sum += __shfl_xor_sync(0xffffffffu, sum, 16);
    sum += __shfl_xor_sync(0xffffffffu, sum, 8);
    sum += __shfl_xor_sync(0xffffffffu, sum, 4);
    sum += __shfl_xor_sync(0xffffffffu, sum, 2);
    sum += __shfl_xor_sync(0xffffffffu, sum, 1);
    const float inv = 1.f / sum;

    // ---- weighted V sum ----
    float acc0 = 0.f, acc1 = 0.f;
#pragma unroll
    for (int o = 0; o < NOFF; o++) {
        const int off = c_offs[o];
        const int src = n - off;
        if (src >= 0) {
            float ev = (o < 32) ? e0 : e1;
            float al = __shfl_sync(0xffffffffu, ev, o & 31);
            const float2 v2 = *(const float2*)(qkv + (size_t)src * H3 + 2 * D + h * 64 + lane * 2);
            acc0 = fmaf(al, v2.x, acc0);
            acc1 = fmaf(al, v2.y, acc1);
        }
    }
    acc0 *= inv;
    acc1 *= inv;

    const int oi = n * D + h * 64 + lane * 2;
    const float2 g2 = *(const float2*)(gate + oi);
    float v0 = acc0 * g2.x;
    float v1 = acc1 * g2.y;

    __nv_bfloat16 h0 = __float2bfloat16(v0);
    __nv_bfloat16 h1 = __float2bfloat16(v1);
    a2h[oi]     = h0;
    a2h[oi + 1] = h1;
    a2l[oi]     = __float2bfloat16(v0 - __bfloat162float(h0));
    a2l[oi + 1] = __float2bfloat16(v1 - __bfloat162float(h1));
}

// ---------------------------------------------------------------------------
// kernel_launch
// ---------------------------------------------------------------------------
extern "C" void kernel_launch(void* const* d_in, const int* in_sizes, int n_in,
                              void* d_out, int out_size)
{
    const float* x        = (const float*)d_in[0];
    const float* Wqkv     = (const float*)d_in[1];
    const float* bqkv     = (const float*)d_in[2];
    const float* Wout     = (const float*)d_in[3];
    const float* bout     = (const float*)d_in[4];
    const float* Wgate    = (const float*)d_in[5];
    const float* bgate    = (const float*)d_in[6];
    const float* pos_bias = (const float*)d_in[7];
    float* out = (float*)d_out;

    float *qkv, *gate;
    __nv_bfloat16 *xh, *xl, *wfh, *wfl, *woh, *wol, *a2h, *a2l;
    cudaGetSymbolAddress((void**)&qkv,  g_qkv);
    cudaGetSymbolAddress((void**)&gate, g_gate);
    cudaGetSymbolAddress((void**)&xh,  g_xh);  cudaGetSymbolAddress((void**)&xl,  g_xl);
    cudaGetSymbolAddress((void**)&wfh, g_wfh); cudaGetSymbolAddress((void**)&wfl, g_wfl);
    cudaGetSymbolAddress((void**)&woh, g_woh); cudaGetSymbolAddress((void**)&wol, g_wol);
    cudaGetSymbolAddress((void**)&a2h, g_a2h); cudaGetSymbolAddress((void**)&a2l, g_a2l);

    const int SMEM_BYTES = 128 + 2 * 32768;   // pad + 2 stages x (A 16K + B 16K)
    cudaFuncSetAttribute(hmma_gemm, cudaFuncAttributeMaxDynamicSharedMemorySize, SMEM_BYTES);

    // 1) all fp32 -> bf16 hi/lo splits (one launch)
    split_all_kernel<<<(TOT4 + 255) / 256, 256>>>(
        (const float4*)x, (const float4*)Wqkv, (const float4*)Wgate, (const float4*)Wout,
        (uint2*)xh, (uint2*)xl, (uint2*)wfh, (uint2*)wfl, (uint2*)woh, (uint2*)wol);

    // 2) fused qkv+gate GEMM: [2048, 4096] = x @ [Wqkv; Wgate]^T
    hmma_gemm<<<dim3((H3 + D) / 128, TOK / 128), 256, SMEM_BYTES>>>(
        xh, xl, wfh, wfl, bqkv, bgate, qkv, gate, H3 + D, D, H3);

    // 3) attention + gate -> split a2
    attn_kernel<<<(TOK * NH) / 8, 256>>>(qkv, gate, pos_bias, a2h, a2l);

    // 4) out = a2 @ Wout^T + bout  (NSPLIT=D -> plain epilogue everywhere)
    hmma_gemm<<<dim3(D / 128, TOK / 128), 256, SMEM_BYTES>>>(
        a2h, a2l, woh, wol, bout, bout, out, nullptr, D, D, D);
}